// round 11
// baseline (speedup 1.0000x reference)
#include <cuda_runtime.h>
#include <cstdint>

#define NMAX 100000
#define EMAX 800000

typedef unsigned long long ULL;

// Scratch (static __device__ arrays per allocation rules)
__device__ float g_h[NMAX * 64];
__device__ float g_agg[NMAX * 64];
__device__ float g_Wf[384 * 64];
__device__ float g_bf[64];
__device__ float g_dinv[NMAX];
__device__ int   g_cnt[NMAX];
__device__ int   g_rowptr[NMAX];
__device__ int   g_pos[NMAX];
__device__ int   g_ssrc[EMAX];
__device__ float g_snorm[EMAX];
__device__ int   g_bsum[128];
__device__ int   g_bscan[128];

// ------------- init + weight fusion (merged: one launch) -------------------

__global__ void k_initfuse(const float* __restrict__ Wm, const float* __restrict__ W1,
                           const float* __restrict__ bm,
                           float* __restrict__ Wf, float* __restrict__ bf, int n) {
    int i = blockIdx.x * blockDim.x + threadIdx.x;
    if (i < n) { g_dinv[i] = 1.0f; g_cnt[i] = 0; }
    if (i < 384 * 64) {
        int r = i >> 6, c = i & 63;
        float s = 0.f;
        #pragma unroll
        for (int k = 0; k < 64; k++) s += Wm[r * 64 + k] * W1[k * 64 + c];
        Wf[i] = s;
    } else if (i < 384 * 64 + 64) {
        int c = i - 384 * 64;
        float s = 0.f;
        #pragma unroll
        for (int k = 0; k < 64; k++) s += bm[k] * W1[k * 64 + c];
        bf[c] = s;
    }
}

// ---------------- preprocessing ----------------

__global__ void k_deg(const int* __restrict__ src, const int* __restrict__ dst,
                      const float* __restrict__ w, int e) {
    int i = blockIdx.x * blockDim.x + threadIdx.x;
    if (i < e) {
        int d = dst[i];
        atomicAdd(&g_dinv[d], w[i]);
        atomicAdd(&g_cnt[d], 1);
    }
}

// scan1 also finalizes dinv = rsqrt(deg)
__global__ void k_scan1(int n) {
    __shared__ int sh[1024];
    int t = threadIdx.x;
    int i = blockIdx.x * 1024 + t;
    if (i < n) g_dinv[i] = rsqrtf(g_dinv[i]);
    int v = (i < n) ? g_cnt[i] : 0;
    sh[t] = v; __syncthreads();
    #pragma unroll
    for (int off = 1; off < 1024; off <<= 1) {
        int x = (t >= off) ? sh[t - off] : 0;
        __syncthreads();
        sh[t] += x;
        __syncthreads();
    }
    if (i < n) g_rowptr[i] = sh[t] - v;
    if (t == 1023) g_bsum[blockIdx.x] = sh[1023];
}

__global__ void k_scan2(int nb) {
    __shared__ int sh[128];
    int t = threadIdx.x;
    int v = (t < nb) ? g_bsum[t] : 0;
    sh[t] = v; __syncthreads();
    #pragma unroll
    for (int off = 1; off < 128; off <<= 1) {
        int x = (t >= off) ? sh[t - off] : 0;
        __syncthreads();
        sh[t] += x;
        __syncthreads();
    }
    if (t < nb) g_bscan[t] = sh[t] - v;
}

__global__ void k_scan3(int n) {
    int i = blockIdx.x * blockDim.x + threadIdx.x;
    if (i < n) {
        int r = g_rowptr[i] + g_bscan[i >> 10];
        g_rowptr[i] = r;
        g_pos[i] = r;
    }
}

__global__ void k_fill(const int* __restrict__ src, const int* __restrict__ dst,
                       const float* __restrict__ w, int e) {
    int i = blockIdx.x * blockDim.x + threadIdx.x;
    if (i < e) {
        int d = dst[i], s = src[i];
        int p = atomicAdd(&g_pos[d], 1);
        g_ssrc[p] = s;
        g_snorm[p] = g_dinv[s] * w[i] * g_dinv[d];
    }
}

// ---------------- FFMA2 GEMM, K-pair packed lanes --------------------------
// C[n,64] = A[n,K] @ W[K,64] (+bias). BM=128, BN=64, BK=16, 256 threads.
// FFMA2 lanes hold (even k, odd k) partial sums; horizontal add at epilogue.
//   - A smem row-major (no transpose; STS.128 loader, LDS.128 = 2 k-pairs)
//   - B smem as k-pair-interleaved float2 records (LDS.128 = 2 cols x 1 k-pair)
//   - zero pack MOVs in the inner loop
// Per 4-k step: 8 LDS.128 (A) + 4 LDS.128 (B) + 64 FFMA2.
// Per-thread tile: 8 rows x 4 cols (acc = 32 ULL). Double-buffered.

__device__ __forceinline__ void ffma2(ULL& d, ULL a, ULL b) {
    asm volatile("fma.rn.f32x2 %0, %1, %2, %0;" : "+l"(d) : "l"(a), "l"(b));
}

__device__ __forceinline__ float2 unpack2(ULL v) {
    float2 r;
    asm("mov.b64 {%0, %1}, %2;" : "=f"(r.x), "=f"(r.y) : "l"(v));
    return r;
}

__global__ __launch_bounds__(256, 2)
void k_gemm(const float* __restrict__ A, const float* __restrict__ W,
            const float* __restrict__ bias, float* __restrict__ C,
            int n, int K) {
    __shared__ float  As[2][128][20];   // row-major A tile, row stride 20 (80B, 16B-aligned)
    __shared__ float2 Bp[2][8][64];     // Bp[kk2][c] = (W[k0+2kk2][c], W[k0+2kk2+1][c])
    int t = threadIdx.x;
    int rowBase = blockIdx.x * 128;
    int ty = t >> 4;          // 0..15 -> rows ty*8 .. ty*8+7
    int tx = t & 15;          // 0..15 -> cols tx*4 .. tx*4+3

    // A loader: 512 float4 over 256 threads -> 2 each (row-major, direct STS.128)
    int ar[2], ac[2];
    #pragma unroll
    for (int l = 0; l < 2; l++) {
        int lin = t + l * 256;
        ar[l] = lin >> 2;          // 0..127
        ac[l] = (lin & 3) * 4;     // 0,4,8,12
    }
    // B loader: thread -> (kk2 = t>>5, col pair cp = (t&31)*2)
    int bk2 = t >> 5;              // 0..7
    int bcp = (t & 31) * 2;        // 0..62

    ULL acc[8][4];
    #pragma unroll
    for (int i = 0; i < 8; i++)
        #pragma unroll
        for (int j = 0; j < 4; j++) acc[i][j] = 0ull;

    int nch = K >> 4;

    // prologue: chunk 0 -> buffer 0
    {
        #pragma unroll
        for (int l = 0; l < 2; l++) {
            int row = rowBase + ar[l];
            float4 v = make_float4(0.f, 0.f, 0.f, 0.f);
            if (row < n) v = *(const float4*)&A[(long)row * K + ac[l]];
            *(float4*)&As[0][ar[l]][ac[l]] = v;
        }
        float2 b0 = *(const float2*)&W[(2 * bk2) * 64 + bcp];
        float2 b1 = *(const float2*)&W[(2 * bk2 + 1) * 64 + bcp];
        *(float4*)&Bp[0][bk2][bcp] = make_float4(b0.x, b1.x, b0.y, b1.y);
    }
    __syncthreads();

    for (int ch = 0; ch < nch; ch++) {
        int buf = ch & 1;
        // issue next chunk's gmem loads first (latency overlaps compute)
        float4 pa[2];
        float2 pb0, pb1;
        bool haveNext = (ch + 1) < nch;
        if (haveNext) {
            int k0 = (ch + 1) << 4;
            #pragma unroll
            for (int l = 0; l < 2; l++) {
                int row = rowBase + ar[l];
                pa[l] = make_float4(0.f, 0.f, 0.f, 0.f);
                if (row < n) pa[l] = *(const float4*)&A[(long)row * K + k0 + ac[l]];
            }
            pb0 = *(const float2*)&W[(k0 + 2 * bk2) * 64 + bcp];
            pb1 = *(const float2*)&W[(k0 + 2 * bk2 + 1) * 64 + bcp];
        }
        // compute from current buffer: 4 steps of 4 k (= 2 k-pairs)
        #pragma unroll
        for (int kp = 0; kp < 4; kp++) {
            ulonglong2 b0a = *(const ulonglong2*)&Bp[buf][2 * kp][tx * 4];       // cols tx*4,+1 @ kk2=2kp
            ulonglong2 b0b = *(const ulonglong2*)&Bp[buf][2 * kp][tx * 4 + 2];   // cols +2,+3
            ulonglong2 b1a = *(const ulonglong2*)&Bp[buf][2 * kp + 1][tx * 4];
            ulonglong2 b1b = *(const ulonglong2*)&Bp[buf][2 * kp + 1][tx * 4 + 2];
            #pragma unroll
            for (int i = 0; i < 8; i++) {
                ulonglong2 av = *(const ulonglong2*)&As[buf][ty * 8 + i][kp * 4]; // (k0,k1),(k2,k3)
                ffma2(acc[i][0], av.x, b0a.x); ffma2(acc[i][0], av.y, b1a.x);
                ffma2(acc[i][1], av.x, b0a.y); ffma2(acc[i][1], av.y, b1a.y);
                ffma2(acc[i][2], av.x, b0b.x); ffma2(acc[i][2], av.y, b1b.x);
                ffma2(acc[i][3], av.x, b0b.y); ffma2(acc[i][3], av.y, b1b.y);
            }
        }
        // store prefetched chunk to alternate buffer
        if (haveNext) {
            int nb2 = buf ^ 1;
            #pragma unroll
            for (int l = 0; l < 2; l++)
                *(float4*)&As[nb2][ar[l]][ac[l]] = pa[l];
            *(float4*)&Bp[nb2][bk2][bcp] = make_float4(pb0.x, pb1.x, pb0.y, pb1.y);
            __syncthreads();
        }
    }

    float bv[4];
    #pragma unroll
    for (int j = 0; j < 4; j++) bv[j] = bias ? bias[tx * 4 + j] : 0.f;

    #pragma unroll
    for (int i = 0; i < 8; i++) {
        int row = rowBase + ty * 8 + i;
        if (row < n) {
            float2 c0 = unpack2(acc[i][0]);
            float2 c1 = unpack2(acc[i][1]);
            float2 c2 = unpack2(acc[i][2]);
            float2 c3 = unpack2(acc[i][3]);
            float4 o = make_float4(c0.x + c0.y + bv[0], c1.x + c1.y + bv[1],
                                   c2.x + c2.y + bv[2], c3.x + c3.y + bv[3]);
            *(float4*)&C[(long)row * 64 + tx * 4] = o;
        }
    }
}

// ------- aggregation: warp per node, float2 per lane (proven R6 version) ---

__global__ void k_agg(const float* __restrict__ h, float* __restrict__ out,
                      const float* __restrict__ bias, int n, int doRelu) {
    int warp = (blockIdx.x * blockDim.x + threadIdx.x) >> 5;
    int lane = threadIdx.x & 31;
    if (warp >= n) return;
    int start = g_rowptr[warp];
    int cnt = g_cnt[warp];
    const float2* hp = (const float2*)h;
    float ax = 0.f, ay = 0.f;
    for (int i = 0; i < cnt; i++) {
        int s = __ldg(&g_ssrc[start + i]);
        float nrm = __ldg(&g_snorm[start + i]);
        float2 v = hp[(long)s * 32 + lane];
        ax += v.x * nrm;
        ay += v.y * nrm;
    }
    float di = g_dinv[warp];
    float sn = di * di;
    float2 sv = hp[(long)warp * 32 + lane];
    ax += sv.x * sn;
    ay += sv.y * sn;
    ax += bias[lane * 2];
    ay += bias[lane * 2 + 1];
    if (doRelu) { ax = fmaxf(ax, 0.f); ay = fmaxf(ay, 0.f); }
    float2 o; o.x = ax; o.y = ay;
    ((float2*)out)[(long)warp * 32 + lane] = o;
}

// ---------------- launcher ----------------
// GEMM0 at launch position 3 (ncu captures the 4th launch).

extern "C" void kernel_launch(void* const* d_in, const int* in_sizes, int n_in,
                              void* d_out, int out_size) {
    const float* x  = (const float*)d_in[0];
    const int*   ei = (const int*)d_in[1];
    const float* w  = (const float*)d_in[2];
    const float* Wm = (const float*)d_in[3];
    const float* bm = (const float*)d_in[4];
    const float* W1 = (const float*)d_in[5];
    const float* b1 = (const float*)d_in[6];
    const float* W2 = (const float*)d_in[7];
    const float* b2 = (const float*)d_in[8];

    int e = in_sizes[2];
    int n = in_sizes[0] / 384;
    const int* src = ei;
    const int* dst = ei + e;

    void *p_h, *p_agg, *p_Wf, *p_bf;
    cudaGetSymbolAddress(&p_h,   g_h);
    cudaGetSymbolAddress(&p_agg, g_agg);
    cudaGetSymbolAddress(&p_Wf,  g_Wf);
    cudaGetSymbolAddress(&p_bf,  g_bf);
    float* h   = (float*)p_h;
    float* agg = (float*)p_agg;
    float* Wf  = (float*)p_Wf;
    float* bf  = (float*)p_bf;

    int nb = (n + 1023) / 1024;

    k_initfuse<<<(n + 255) / 256, 256>>>(Wm, W1, bm, Wf, bf, n);   // 0
    k_deg<<<(e + 255) / 256, 256>>>(src, dst, w, e);               // 1
    k_scan1<<<nb, 1024>>>(n);                                      // 2
    k_gemm<<<(n + 127) / 128, 256>>>(x, Wf, bf, h, n, 384);        // 3 (profiled)
    k_scan2<<<1, 128>>>(nb);                                       // 4
    k_scan3<<<(n + 255) / 256, 256>>>(n);                          // 5
    k_fill<<<(e + 255) / 256, 256>>>(src, dst, w, e);              // 6
    k_agg<<<(n + 7) / 8, 256>>>(h, agg, b1, n, 1);                 // 7
    k_gemm<<<(n + 127) / 128, 256>>>(agg, W2, nullptr, h, n, 64);  // 8
    k_agg<<<(n + 7) / 8, 256>>>(h, (float*)d_out, b2, n, 0);       // 9
}

// round 12
// speedup vs baseline: 1.3907x; 1.3907x over previous
#include <cuda_runtime.h>
#include <cstdint>

#define NMAX 100000
#define EMAX 800000

typedef unsigned long long ULL;

// Scratch (static __device__ arrays per allocation rules)
__device__ float g_h[NMAX * 64];
__device__ float g_agg[NMAX * 64];
__device__ float g_Wf[384 * 64];
__device__ float g_bf[64];
__device__ float g_dinv[NMAX];
__device__ int   g_cnt[NMAX];
__device__ int   g_rowptr[NMAX];
__device__ int   g_pos[NMAX];
__device__ int   g_ssrc[EMAX];
__device__ float g_snorm[EMAX];
__device__ int   g_bsum[128];
__device__ int   g_bscan[128];

// ------------- init + weight fusion (merged: one launch) -------------------

__global__ void k_initfuse(const float* __restrict__ Wm, const float* __restrict__ W1,
                           const float* __restrict__ bm,
                           float* __restrict__ Wf, float* __restrict__ bf, int n) {
    int i = blockIdx.x * blockDim.x + threadIdx.x;
    if (i < n) { g_dinv[i] = 1.0f; g_cnt[i] = 0; }
    if (i < 384 * 64) {
        int r = i >> 6, c = i & 63;
        float s = 0.f;
        #pragma unroll
        for (int k = 0; k < 64; k++) s += Wm[r * 64 + k] * W1[k * 64 + c];
        Wf[i] = s;
    } else if (i < 384 * 64 + 64) {
        int c = i - 384 * 64;
        float s = 0.f;
        #pragma unroll
        for (int k = 0; k < 64; k++) s += bm[k] * W1[k * 64 + c];
        bf[c] = s;
    }
}

// ---------------- preprocessing ----------------

__global__ void k_deg(const int* __restrict__ src, const int* __restrict__ dst,
                      const float* __restrict__ w, int e) {
    int i = blockIdx.x * blockDim.x + threadIdx.x;
    if (i < e) {
        int d = dst[i];
        atomicAdd(&g_dinv[d], w[i]);
        atomicAdd(&g_cnt[d], 1);
    }
}

// scan1 also finalizes dinv = rsqrt(deg)
__global__ void k_scan1(int n) {
    __shared__ int sh[1024];
    int t = threadIdx.x;
    int i = blockIdx.x * 1024 + t;
    if (i < n) g_dinv[i] = rsqrtf(g_dinv[i]);
    int v = (i < n) ? g_cnt[i] : 0;
    sh[t] = v; __syncthreads();
    #pragma unroll
    for (int off = 1; off < 1024; off <<= 1) {
        int x = (t >= off) ? sh[t - off] : 0;
        __syncthreads();
        sh[t] += x;
        __syncthreads();
    }
    if (i < n) g_rowptr[i] = sh[t] - v;
    if (t == 1023) g_bsum[blockIdx.x] = sh[1023];
}

__global__ void k_scan2(int nb) {
    __shared__ int sh[128];
    int t = threadIdx.x;
    int v = (t < nb) ? g_bsum[t] : 0;
    sh[t] = v; __syncthreads();
    #pragma unroll
    for (int off = 1; off < 128; off <<= 1) {
        int x = (t >= off) ? sh[t - off] : 0;
        __syncthreads();
        sh[t] += x;
        __syncthreads();
    }
    if (t < nb) g_bscan[t] = sh[t] - v;
}

__global__ void k_scan3(int n) {
    int i = blockIdx.x * blockDim.x + threadIdx.x;
    if (i < n) {
        int r = g_rowptr[i] + g_bscan[i >> 10];
        g_rowptr[i] = r;
        g_pos[i] = r;
    }
}

__global__ void k_fill(const int* __restrict__ src, const int* __restrict__ dst,
                       const float* __restrict__ w, int e) {
    int i = blockIdx.x * blockDim.x + threadIdx.x;
    if (i < e) {
        int d = dst[i], s = src[i];
        int p = atomicAdd(&g_pos[d], 1);
        g_ssrc[p] = s;
        g_snorm[p] = g_dinv[s] * w[i] * g_dinv[d];
    }
}

// ---------------- FFMA2 GEMM, double-buffered (R6 layout) ------------------
// C[n,64] = A[n,K] @ W[K,64] (+bias). BM=128, BN=64, BK=16, 256 threads.
// ONE change vs the proven 252.7us version: ffma2/pack2 are NON-volatile so
// ptxas may schedule FMAs, rotate accumulators, and overlap LDS/MOVs.

__device__ __forceinline__ void ffma2(ULL& d, ULL a, ULL b) {
    asm("fma.rn.f32x2 %0, %1, %2, %0;" : "+l"(d) : "l"(a), "l"(b));
}

__device__ __forceinline__ ULL pack2(float v) {
    ULL r;
    asm("mov.b64 %0, {%1, %1};" : "=l"(r) : "f"(v));
    return r;
}

__device__ __forceinline__ float2 unpack2(ULL v) {
    float2 r;
    asm("mov.b64 {%0, %1}, %2;" : "=f"(r.x), "=f"(r.y) : "l"(v));
    return r;
}

__global__ __launch_bounds__(256)
void k_gemm(const float* __restrict__ A, const float* __restrict__ W,
            const float* __restrict__ bias, float* __restrict__ C,
            int n, int K) {
    __shared__ float As[2][16][132];
    __shared__ float Bs[2][16][64];
    int t = threadIdx.x;
    int rowBase = blockIdx.x * 128;
    int ty = t >> 4;
    int tx = t & 15;

    int ar[2], ac[2];
    #pragma unroll
    for (int l = 0; l < 2; l++) {
        int lin = t + l * 256;
        ar[l] = lin >> 2;
        ac[l] = (lin & 3) * 4;
    }
    int bkr = t >> 4;
    int bc  = (t & 15) * 4;

    ULL acc[4][4];
    #pragma unroll
    for (int i = 0; i < 4; i++)
        #pragma unroll
        for (int j = 0; j < 4; j++) acc[i][j] = 0ull;

    int nch = K >> 4;

    {
        #pragma unroll
        for (int l = 0; l < 2; l++) {
            int row = rowBase + ar[l];
            float4 v = make_float4(0.f, 0.f, 0.f, 0.f);
            if (row < n) v = *(const float4*)&A[(long)row * K + ac[l]];
            As[0][ac[l] + 0][ar[l]] = v.x;
            As[0][ac[l] + 1][ar[l]] = v.y;
            As[0][ac[l] + 2][ar[l]] = v.z;
            As[0][ac[l] + 3][ar[l]] = v.w;
        }
        *(float4*)&Bs[0][bkr][bc] = *(const float4*)&W[bkr * 64 + bc];
    }
    __syncthreads();

    for (int ch = 0; ch < nch; ch++) {
        int buf = ch & 1;
        float4 pa[2];
        float4 pb;
        bool haveNext = (ch + 1) < nch;
        if (haveNext) {
            int k0 = (ch + 1) << 4;
            #pragma unroll
            for (int l = 0; l < 2; l++) {
                int row = rowBase + ar[l];
                pa[l] = make_float4(0.f, 0.f, 0.f, 0.f);
                if (row < n) pa[l] = *(const float4*)&A[(long)row * K + k0 + ac[l]];
            }
            pb = *(const float4*)&W[(k0 + bkr) * 64 + bc];
        }
        #pragma unroll
        for (int kk = 0; kk < 16; kk++) {
            ULL a2[4];
            #pragma unroll
            for (int i = 0; i < 4; i++)
                a2[i] = *(const ULL*)&As[buf][kk][ty * 8 + 2 * i];
            float4 b4 = *(const float4*)&Bs[buf][kk][tx * 4];
            ULL bb[4];
            bb[0] = pack2(b4.x); bb[1] = pack2(b4.y);
            bb[2] = pack2(b4.z); bb[3] = pack2(b4.w);
            #pragma unroll
            for (int i = 0; i < 4; i++)
                #pragma unroll
                for (int j = 0; j < 4; j++)
                    ffma2(acc[i][j], a2[i], bb[j]);
        }
        if (haveNext) {
            int nb2 = buf ^ 1;
            #pragma unroll
            for (int l = 0; l < 2; l++) {
                As[nb2][ac[l] + 0][ar[l]] = pa[l].x;
                As[nb2][ac[l] + 1][ar[l]] = pa[l].y;
                As[nb2][ac[l] + 2][ar[l]] = pa[l].z;
                As[nb2][ac[l] + 3][ar[l]] = pa[l].w;
            }
            *(float4*)&Bs[nb2][bkr][bc] = pb;
            __syncthreads();
        }
    }

    float bv[4];
    #pragma unroll
    for (int j = 0; j < 4; j++) bv[j] = bias ? bias[tx * 4 + j] : 0.f;

    #pragma unroll
    for (int i = 0; i < 4; i++) {
        int row0 = rowBase + ty * 8 + 2 * i;
        float2 c0 = unpack2(acc[i][0]);
        float2 c1 = unpack2(acc[i][1]);
        float2 c2 = unpack2(acc[i][2]);
        float2 c3 = unpack2(acc[i][3]);
        if (row0 < n) {
            float4 o = make_float4(c0.x + bv[0], c1.x + bv[1], c2.x + bv[2], c3.x + bv[3]);
            *(float4*)&C[(long)row0 * 64 + tx * 4] = o;
        }
        if (row0 + 1 < n) {
            float4 o = make_float4(c0.y + bv[0], c1.y + bv[1], c2.y + bv[2], c3.y + bv[3]);
            *(float4*)&C[(long)(row0 + 1) * 64 + tx * 4] = o;
        }
    }
}

// ------- aggregation: warp per node, float2 per lane (proven R6 version) ---

__global__ void k_agg(const float* __restrict__ h, float* __restrict__ out,
                      const float* __restrict__ bias, int n, int doRelu) {
    int warp = (blockIdx.x * blockDim.x + threadIdx.x) >> 5;
    int lane = threadIdx.x & 31;
    if (warp >= n) return;
    int start = g_rowptr[warp];
    int cnt = g_cnt[warp];
    const float2* hp = (const float2*)h;
    float ax = 0.f, ay = 0.f;
    for (int i = 0; i < cnt; i++) {
        int s = __ldg(&g_ssrc[start + i]);
        float nrm = __ldg(&g_snorm[start + i]);
        float2 v = hp[(long)s * 32 + lane];
        ax += v.x * nrm;
        ay += v.y * nrm;
    }
    float di = g_dinv[warp];
    float sn = di * di;
    float2 sv = hp[(long)warp * 32 + lane];
    ax += sv.x * sn;
    ay += sv.y * sn;
    ax += bias[lane * 2];
    ay += bias[lane * 2 + 1];
    if (doRelu) { ax = fmaxf(ax, 0.f); ay = fmaxf(ay, 0.f); }
    float2 o; o.x = ax; o.y = ay;
    ((float2*)out)[(long)warp * 32 + lane] = o;
}

// ---------------- launcher ----------------
// GEMM0 at launch position 3 (ncu captures the 4th launch).

extern "C" void kernel_launch(void* const* d_in, const int* in_sizes, int n_in,
                              void* d_out, int out_size) {
    const float* x  = (const float*)d_in[0];
    const int*   ei = (const int*)d_in[1];
    const float* w  = (const float*)d_in[2];
    const float* Wm = (const float*)d_in[3];
    const float* bm = (const float*)d_in[4];
    const float* W1 = (const float*)d_in[5];
    const float* b1 = (const float*)d_in[6];
    const float* W2 = (const float*)d_in[7];
    const float* b2 = (const float*)d_in[8];

    int e = in_sizes[2];
    int n = in_sizes[0] / 384;
    const int* src = ei;
    const int* dst = ei + e;

    void *p_h, *p_agg, *p_Wf, *p_bf;
    cudaGetSymbolAddress(&p_h,   g_h);
    cudaGetSymbolAddress(&p_agg, g_agg);
    cudaGetSymbolAddress(&p_Wf,  g_Wf);
    cudaGetSymbolAddress(&p_bf,  g_bf);
    float* h   = (float*)p_h;
    float* agg = (float*)p_agg;
    float* Wf  = (float*)p_Wf;
    float* bf  = (float*)p_bf;

    int nb = (n + 1023) / 1024;

    k_initfuse<<<(n + 255) / 256, 256>>>(Wm, W1, bm, Wf, bf, n);   // 0
    k_deg<<<(e + 255) / 256, 256>>>(src, dst, w, e);               // 1
    k_scan1<<<nb, 1024>>>(n);                                      // 2
    k_gemm<<<(n + 127) / 128, 256>>>(x, Wf, bf, h, n, 384);        // 3 (profiled)
    k_scan2<<<1, 128>>>(nb);                                       // 4
    k_scan3<<<(n + 255) / 256, 256>>>(n);                          // 5
    k_fill<<<(e + 255) / 256, 256>>>(src, dst, w, e);              // 6
    k_agg<<<(n + 7) / 8, 256>>>(h, agg, b1, n, 1);                 // 7
    k_gemm<<<(n + 127) / 128, 256>>>(agg, W2, nullptr, h, n, 64);  // 8
    k_agg<<<(n + 7) / 8, 256>>>(h, (float*)d_out, b2, n, 0);       // 9
}

// round 13
// speedup vs baseline: 1.5431x; 1.1096x over previous
#include <cuda_runtime.h>
#include <cstdint>

#define NMAX 100000
#define EMAX 800000

typedef unsigned long long ULL;

// Scratch (static __device__ arrays per allocation rules)
__device__ float g_h[NMAX * 64];
__device__ float g_agg[NMAX * 64];
__device__ float g_Wf[384 * 64];
__device__ float g_bf[64];
__device__ float g_dinv[NMAX];
__device__ int   g_cnt[NMAX];
__device__ int   g_rowptr[NMAX];
__device__ int   g_pos[NMAX];
__device__ int   g_ssrc[EMAX];
__device__ float g_snorm[EMAX];
__device__ int   g_bsum[128];
__device__ int   g_bscan[128];

// ------------- init + weight fusion (merged: one launch) -------------------

__global__ void k_initfuse(const float* __restrict__ Wm, const float* __restrict__ W1,
                           const float* __restrict__ bm,
                           float* __restrict__ Wf, float* __restrict__ bf, int n) {
    int i = blockIdx.x * blockDim.x + threadIdx.x;
    if (i < n) { g_dinv[i] = 1.0f; g_cnt[i] = 0; }
    if (i < 384 * 64) {
        int r = i >> 6, c = i & 63;
        float s = 0.f;
        #pragma unroll
        for (int k = 0; k < 64; k++) s += Wm[r * 64 + k] * W1[k * 64 + c];
        Wf[i] = s;
    } else if (i < 384 * 64 + 64) {
        int c = i - 384 * 64;
        float s = 0.f;
        #pragma unroll
        for (int k = 0; k < 64; k++) s += bm[k] * W1[k * 64 + c];
        bf[c] = s;
    }
}

// ---------------- preprocessing ----------------

__global__ void k_deg(const int* __restrict__ src, const int* __restrict__ dst,
                      const float* __restrict__ w, int e) {
    int i = blockIdx.x * blockDim.x + threadIdx.x;
    if (i < e) {
        int d = dst[i];
        atomicAdd(&g_dinv[d], w[i]);
        atomicAdd(&g_cnt[d], 1);
    }
}

// scan1 also finalizes dinv = rsqrt(deg)
__global__ void k_scan1(int n) {
    __shared__ int sh[1024];
    int t = threadIdx.x;
    int i = blockIdx.x * 1024 + t;
    if (i < n) g_dinv[i] = rsqrtf(g_dinv[i]);
    int v = (i < n) ? g_cnt[i] : 0;
    sh[t] = v; __syncthreads();
    #pragma unroll
    for (int off = 1; off < 1024; off <<= 1) {
        int x = (t >= off) ? sh[t - off] : 0;
        __syncthreads();
        sh[t] += x;
        __syncthreads();
    }
    if (i < n) g_rowptr[i] = sh[t] - v;
    if (t == 1023) g_bsum[blockIdx.x] = sh[1023];
}

__global__ void k_scan2(int nb) {
    __shared__ int sh[128];
    int t = threadIdx.x;
    int v = (t < nb) ? g_bsum[t] : 0;
    sh[t] = v; __syncthreads();
    #pragma unroll
    for (int off = 1; off < 128; off <<= 1) {
        int x = (t >= off) ? sh[t - off] : 0;
        __syncthreads();
        sh[t] += x;
        __syncthreads();
    }
    if (t < nb) g_bscan[t] = sh[t] - v;
}

__global__ void k_scan3(int n) {
    int i = blockIdx.x * blockDim.x + threadIdx.x;
    if (i < n) {
        int r = g_rowptr[i] + g_bscan[i >> 10];
        g_rowptr[i] = r;
        g_pos[i] = r;
    }
}

__global__ void k_fill(const int* __restrict__ src, const int* __restrict__ dst,
                       const float* __restrict__ w, int e) {
    int i = blockIdx.x * blockDim.x + threadIdx.x;
    if (i < e) {
        int d = dst[i], s = src[i];
        int p = atomicAdd(&g_pos[d], 1);
        g_ssrc[p] = s;
        g_snorm[p] = g_dinv[s] * w[i] * g_dinv[d];
    }
}

// ---------------- FFMA2 GEMM, double-buffered (R12, proven 123.6us) --------

__device__ __forceinline__ void ffma2(ULL& d, ULL a, ULL b) {
    asm("fma.rn.f32x2 %0, %1, %2, %0;" : "+l"(d) : "l"(a), "l"(b));
}

__device__ __forceinline__ ULL pack2(float v) {
    ULL r;
    asm("mov.b64 %0, {%1, %1};" : "=l"(r) : "f"(v));
    return r;
}

__device__ __forceinline__ float2 unpack2(ULL v) {
    float2 r;
    asm("mov.b64 {%0, %1}, %2;" : "=f"(r.x), "=f"(r.y) : "l"(v));
    return r;
}

__global__ __launch_bounds__(256)
void k_gemm(const float* __restrict__ A, const float* __restrict__ W,
            const float* __restrict__ bias, float* __restrict__ C,
            int n, int K) {
    __shared__ float As[2][16][132];
    __shared__ float Bs[2][16][64];
    int t = threadIdx.x;
    int rowBase = blockIdx.x * 128;
    int ty = t >> 4;
    int tx = t & 15;

    int ar[2], ac[2];
    #pragma unroll
    for (int l = 0; l < 2; l++) {
        int lin = t + l * 256;
        ar[l] = lin >> 2;
        ac[l] = (lin & 3) * 4;
    }
    int bkr = t >> 4;
    int bc  = (t & 15) * 4;

    ULL acc[4][4];
    #pragma unroll
    for (int i = 0; i < 4; i++)
        #pragma unroll
        for (int j = 0; j < 4; j++) acc[i][j] = 0ull;

    int nch = K >> 4;

    {
        #pragma unroll
        for (int l = 0; l < 2; l++) {
            int row = rowBase + ar[l];
            float4 v = make_float4(0.f, 0.f, 0.f, 0.f);
            if (row < n) v = *(const float4*)&A[(long)row * K + ac[l]];
            As[0][ac[l] + 0][ar[l]] = v.x;
            As[0][ac[l] + 1][ar[l]] = v.y;
            As[0][ac[l] + 2][ar[l]] = v.z;
            As[0][ac[l] + 3][ar[l]] = v.w;
        }
        *(float4*)&Bs[0][bkr][bc] = *(const float4*)&W[bkr * 64 + bc];
    }
    __syncthreads();

    for (int ch = 0; ch < nch; ch++) {
        int buf = ch & 1;
        float4 pa[2];
        float4 pb;
        bool haveNext = (ch + 1) < nch;
        if (haveNext) {
            int k0 = (ch + 1) << 4;
            #pragma unroll
            for (int l = 0; l < 2; l++) {
                int row = rowBase + ar[l];
                pa[l] = make_float4(0.f, 0.f, 0.f, 0.f);
                if (row < n) pa[l] = *(const float4*)&A[(long)row * K + k0 + ac[l]];
            }
            pb = *(const float4*)&W[(k0 + bkr) * 64 + bc];
        }
        #pragma unroll
        for (int kk = 0; kk < 16; kk++) {
            ULL a2[4];
            #pragma unroll
            for (int i = 0; i < 4; i++)
                a2[i] = *(const ULL*)&As[buf][kk][ty * 8 + 2 * i];
            float4 b4 = *(const float4*)&Bs[buf][kk][tx * 4];
            ULL bb[4];
            bb[0] = pack2(b4.x); bb[1] = pack2(b4.y);
            bb[2] = pack2(b4.z); bb[3] = pack2(b4.w);
            #pragma unroll
            for (int i = 0; i < 4; i++)
                #pragma unroll
                for (int j = 0; j < 4; j++)
                    ffma2(acc[i][j], a2[i], bb[j]);
        }
        if (haveNext) {
            int nb2 = buf ^ 1;
            #pragma unroll
            for (int l = 0; l < 2; l++) {
                As[nb2][ac[l] + 0][ar[l]] = pa[l].x;
                As[nb2][ac[l] + 1][ar[l]] = pa[l].y;
                As[nb2][ac[l] + 2][ar[l]] = pa[l].z;
                As[nb2][ac[l] + 3][ar[l]] = pa[l].w;
            }
            *(float4*)&Bs[nb2][bkr][bc] = pb;
            __syncthreads();
        }
    }

    float bv[4];
    #pragma unroll
    for (int j = 0; j < 4; j++) bv[j] = bias ? bias[tx * 4 + j] : 0.f;

    #pragma unroll
    for (int i = 0; i < 4; i++) {
        int row0 = rowBase + ty * 8 + 2 * i;
        float2 c0 = unpack2(acc[i][0]);
        float2 c1 = unpack2(acc[i][1]);
        float2 c2 = unpack2(acc[i][2]);
        float2 c3 = unpack2(acc[i][3]);
        if (row0 < n) {
            float4 o = make_float4(c0.x + bv[0], c1.x + bv[1], c2.x + bv[2], c3.x + bv[3]);
            *(float4*)&C[(long)row0 * 64 + tx * 4] = o;
        }
        if (row0 + 1 < n) {
            float4 o = make_float4(c0.y + bv[0], c1.y + bv[1], c2.y + bv[2], c3.y + bv[3]);
            *(float4*)&C[(long)(row0 + 1) * 64 + tx * 4] = o;
        }
    }
}

// ------- aggregation: warp per node, float2 per lane (proven R6 version) ---

__global__ void k_agg(const float* __restrict__ h, float* __restrict__ out,
                      const float* __restrict__ bias, int n, int doRelu) {
    int warp = (blockIdx.x * blockDim.x + threadIdx.x) >> 5;
    int lane = threadIdx.x & 31;
    if (warp >= n) return;
    int start = g_rowptr[warp];
    int cnt = g_cnt[warp];
    const float2* hp = (const float2*)h;
    float ax = 0.f, ay = 0.f;
    for (int i = 0; i < cnt; i++) {
        int s = __ldg(&g_ssrc[start + i]);
        float nrm = __ldg(&g_snorm[start + i]);
        float2 v = hp[(long)s * 32 + lane];
        ax += v.x * nrm;
        ay += v.y * nrm;
    }
    float di = g_dinv[warp];
    float sn = di * di;
    float2 sv = hp[(long)warp * 32 + lane];
    ax += sv.x * sn;
    ay += sv.y * sn;
    ax += bias[lane * 2];
    ay += bias[lane * 2 + 1];
    if (doRelu) { ax = fmaxf(ax, 0.f); ay = fmaxf(ay, 0.f); }
    float2 o; o.x = ax; o.y = ay;
    ((float2*)out)[(long)warp * 32 + lane] = o;
}

// ---------------- launcher: two-branch graph -------------------------------
// Branch A (default stream): CSR build (deg -> scans -> fill)
// Branch B (side stream):    GEMM0 (only needs Wf/bf from initfuse)
// The branches run concurrently in the captured graph; they join before agg1.

extern "C" void kernel_launch(void* const* d_in, const int* in_sizes, int n_in,
                              void* d_out, int out_size) {
    const float* x  = (const float*)d_in[0];
    const int*   ei = (const int*)d_in[1];
    const float* w  = (const float*)d_in[2];
    const float* Wm = (const float*)d_in[3];
    const float* bm = (const float*)d_in[4];
    const float* W1 = (const float*)d_in[5];
    const float* b1 = (const float*)d_in[6];
    const float* W2 = (const float*)d_in[7];
    const float* b2 = (const float*)d_in[8];

    int e = in_sizes[2];
    int n = in_sizes[0] / 384;
    const int* src = ei;
    const int* dst = ei + e;

    void *p_h, *p_agg, *p_Wf, *p_bf;
    cudaGetSymbolAddress(&p_h,   g_h);
    cudaGetSymbolAddress(&p_agg, g_agg);
    cudaGetSymbolAddress(&p_Wf,  g_Wf);
    cudaGetSymbolAddress(&p_bf,  g_bf);
    float* h   = (float*)p_h;
    float* agg = (float*)p_agg;
    float* Wf  = (float*)p_Wf;
    float* bf  = (float*)p_bf;

    int nb = (n + 1023) / 1024;

    // side stream + events (host-side handles only; no device memory)
    cudaStream_t s2;
    cudaStreamCreateWithFlags(&s2, cudaStreamNonBlocking);
    cudaEvent_t evInit, evGemm;
    cudaEventCreateWithFlags(&evInit, cudaEventDisableTiming);
    cudaEventCreateWithFlags(&evGemm, cudaEventDisableTiming);

    // 0: init + fused weights (both branches depend on this)
    k_initfuse<<<(n + 255) / 256, 256>>>(Wm, W1, bm, Wf, bf, n);
    cudaEventRecord(evInit, 0);
    cudaStreamWaitEvent(s2, evInit, 0);

    // Branch A (default stream): CSR build
    k_deg<<<(e + 255) / 256, 256>>>(src, dst, w, e);               // 1
    k_scan1<<<nb, 1024>>>(n);                                      // 2

    // Branch B (side stream): layer-1 fused GEMM (host-order index 3: profiled)
    k_gemm<<<(n + 127) / 128, 256, 0, s2>>>(x, Wf, bf, h, n, 384); // 3

    k_scan2<<<1, 128>>>(nb);                                       // 4
    k_scan3<<<(n + 255) / 256, 256>>>(n);                          // 5
    k_fill<<<(e + 255) / 256, 256>>>(src, dst, w, e);              // 6

    // join: agg1 needs both h (branch B) and CSR (branch A)
    cudaEventRecord(evGemm, s2);
    cudaStreamWaitEvent(0, evGemm, 0);

    k_agg<<<(n + 7) / 8, 256>>>(h, agg, b1, n, 1);                 // 7
    k_gemm<<<(n + 127) / 128, 256>>>(agg, W2, nullptr, h, n, 64);  // 8
    k_agg<<<(n + 7) / 8, 256>>>(h, (float*)d_out, b2, n, 0);       // 9

    // handles intentionally not destroyed (no device memory; a few calls total)
}